// round 12
// baseline (speedup 1.0000x reference)
#include <cuda_runtime.h>
#include <cuda_fp16.h>
#include <math_constants.h>
#include <mma.h>

using namespace nvcuda;

#define N_NODES   262144
#define D_IN      512
#define B_GRAPHS  256
#define GATES     2048      // 4*D_IN
#define K_COMB    1024      // combined K (h:512 | r:512)
#define STEPS     6
#define CHUNK     896       // nodes per attention block (293 blocks = 1 wave @ 2 CTA/SM)
#define N_CHUNKS  ((N_NODES + CHUNK - 1) / CHUNK)   // 293
#define MAX_SLOTS 8
#define GK        32        // GEMM k-chunk

// ----------------- device scratch (no runtime allocation allowed) -----------
__device__ __align__(16) __half g_W16[GATES * K_COMB];    // fp16 combined weights (4 MB)
__device__ __align__(16) float  g_bias[GATES];
__device__ __align__(16) float  g_hr[B_GRAPHS * 1024];    // [h | r] = q_star (fp32)
__device__ __align__(16) __half g_hr16[B_GRAPHS * 1024];  // fp16 copy for GEMM
__device__ __align__(16) float  g_c[B_GRAPHS * D_IN];
__device__ __align__(16) __half g_x16[(size_t)N_NODES * D_IN];  // 256 MB fp16 copy
__device__ int g_off[B_GRAPHS + 1];
__device__ __align__(16) float g_part_r[B_GRAPHS * MAX_SLOTS * D_IN];
__device__ float g_part_m[B_GRAPHS * MAX_SLOTS];
__device__ float g_part_d[B_GRAPHS * MAX_SLOTS];

// ----------------------------- helpers --------------------------------------
__device__ __forceinline__ float sigm(float v) {
    return 1.0f / (1.0f + __expf(-v));
}

// --------------------------- prep kernels -----------------------------------
__global__ void prep_w_kernel(const float* __restrict__ w_ih,
                              const float* __restrict__ w_hh,
                              const float* __restrict__ b_ih,
                              const float* __restrict__ b_hh) {
    int idx = blockIdx.x * blockDim.x + threadIdx.x;
    int n = idx >> 10;
    int k = idx & 1023;
    float v = w_ih[n * 1024 + k];
    if (k < 512) v += w_hh[n * 512 + k];
    g_W16[idx] = __float2half_rn(v);
    if (idx < GATES) g_bias[idx] = b_ih[idx] + b_hh[idx];
}

__global__ void offsets_kernel(const int* __restrict__ batch) {
    int t = blockIdx.x * blockDim.x + threadIdx.x;
    if (t > B_GRAPHS) return;
    int lo = 0, hi = N_NODES;
    while (lo < hi) {
        int mid = (lo + hi) >> 1;
        if (batch[mid] < t) lo = mid + 1; else hi = mid;
    }
    g_off[t] = lo;
}

// Step 0: q_star = 0, h = 0 -> gates = bias (identical for every graph)
__global__ void lstm_init_kernel() {
    int b = blockIdx.x;
    int d = threadIdx.x;
    float i = sigm(g_bias[d]);
    float g = tanhf(g_bias[1024 + d]);
    float o = sigm(g_bias[1536 + d]);
    float c = i * g;
    float h = o * tanhf(c);
    g_c[b * D_IN + d]  = c;
    g_hr[b * 1024 + d] = h;
    g_hr16[b * 1024 + d] = __float2half_rn(h);
}

// ------ fused GEMM (fp16 HMMA) + LSTM pointwise: h,c = lstm(hr @ W^T) --------
// Grid (16, 4). CTA: rows [bm, bm+64), dims [bn32, bn32+32), ALL FOUR gates
// (tile N = 128 = 4 gates x 32 dims). Epilogue applies the LSTM cell in-kernel.
__global__ void __launch_bounds__(256) gemm_lstm_kernel() {
    __shared__ __align__(16) __half sA[64][GK + 8];    // 5 KB
    __shared__ __align__(16) __half sB[128][GK + 8];   // 10 KB
    __shared__ __align__(16) float  sG[64][128];       // 32 KB

    const int bn32 = blockIdx.x * 32;      // dim offset in [0, 512)
    const int bm   = blockIdx.y * 64;      // row offset in [0, 256)
    const int tid  = threadIdx.x;
    const int w    = tid >> 5;
    const int mw   = w & 1;                // 2 row-warps (32 rows)
    const int nw   = w >> 1;               // 4 col-warps (32 cols)

    wmma::fragment<wmma::accumulator, 16, 16, 16, float> cf[2][2];
    #pragma unroll
    for (int i = 0; i < 2; i++)
        #pragma unroll
        for (int j = 0; j < 2; j++) wmma::fill_fragment(cf[i][j], 0.0f);

    // A staging: 64 rows x 32 halves, one uint4 per thread
    const int ar = tid >> 2;               // 0..63
    const int ac = (tid & 3) * 8;          // 0,8,16,24
    const __half* Ag = g_hr16 + (bm + ar) * K_COMB + ac;
    // B staging: 128 rows x 32 halves, two uint4 per thread
    const int br = tid >> 1;               // 0..127
    const int bc = (tid & 1) * 16;         // 0 or 16
    const int wrow = (br >> 5) * 512 + bn32 + (br & 31);   // gate*512 + dim
    const __half* Bg = g_W16 + wrow * K_COMB + bc;

    uint4 a  = *(const uint4*)(Ag);
    uint4 b0 = *(const uint4*)(Bg);
    uint4 b1 = *(const uint4*)(Bg + 8);

    for (int k0 = 0; k0 < K_COMB; k0 += GK) {
        *(uint4*)&sA[ar][ac]     = a;
        *(uint4*)&sB[br][bc]     = b0;
        *(uint4*)&sB[br][bc + 8] = b1;
        __syncthreads();

        if (k0 + GK < K_COMB) {
            a  = *(const uint4*)(Ag + k0 + GK);
            b0 = *(const uint4*)(Bg + k0 + GK);
            b1 = *(const uint4*)(Bg + k0 + GK + 8);
        }

        #pragma unroll
        for (int kk = 0; kk < GK; kk += 16) {
            wmma::fragment<wmma::matrix_a, 16, 16, 16, __half, wmma::row_major> af[2];
            #pragma unroll
            for (int i = 0; i < 2; i++)
                wmma::load_matrix_sync(af[i], &sA[mw * 32 + i * 16][kk], GK + 8);
            wmma::fragment<wmma::matrix_b, 16, 16, 16, __half, wmma::col_major> bf[2];
            #pragma unroll
            for (int j = 0; j < 2; j++)
                wmma::load_matrix_sync(bf[j], &sB[nw * 32 + j * 16][kk], GK + 8);
            #pragma unroll
            for (int i = 0; i < 2; i++)
                #pragma unroll
                for (int j = 0; j < 2; j++)
                    wmma::mma_sync(cf[i][j], af[i], bf[j], cf[i][j]);
        }
        __syncthreads();
    }

    // accumulators -> smem
    #pragma unroll
    for (int i = 0; i < 2; i++)
        #pragma unroll
        for (int j = 0; j < 2; j++)
            wmma::store_matrix_sync(&sG[mw * 32 + i * 16][nw * 32 + j * 16],
                                    cf[i][j], 128, wmma::mem_row_major);
    __syncthreads();

    // ---- LSTM pointwise epilogue: 64 rows x 32 dims, 8 elems/thread ----
    const int dd = tid & 31;
    const int r0 = tid >> 5;
    const int d  = bn32 + dd;
    const float bi = g_bias[d];
    const float bf_ = g_bias[512 + d];
    const float bg = g_bias[1024 + d];
    const float bo = g_bias[1536 + d];
    #pragma unroll
    for (int k = 0; k < 8; k++) {
        const int r = r0 + k * 8;
        const int brow = bm + r;
        const float iv = sigm(sG[r][dd]       + bi);
        const float fv = sigm(sG[r][32 + dd]  + bf_);
        const float gv = tanhf(sG[r][64 + dd] + bg);
        const float ov = sigm(sG[r][96 + dd]  + bo);
        const int cidx = brow * D_IN + d;
        const float c = fv * g_c[cidx] + iv * gv;
        g_c[cidx] = c;
        const float h = ov * tanhf(c);
        g_hr[brow * 1024 + d]   = h;               // q = h into hr[:, :512]
        g_hr16[brow * 1024 + d] = __float2half_rn(h);
    }
}

// ---------- attention step 0: fp32 sweep + write fp16 copy of x --------------
// Warp-per-node online softmax; col layout slot j*4+c <-> column 128*j+4*lane+c.
__global__ void __launch_bounds__(512, 2) attn0_kernel(const float* __restrict__ x) {
    const int chunk = blockIdx.x;
    const int i0 = chunk * CHUNK;
    const int i1 = min(i0 + CHUNK, N_NODES);
    const int tid  = threadIdx.x;
    const int wid  = tid >> 5;
    const int lane = tid & 31;

    __shared__ __align__(16) float sm_q[D_IN];
    __shared__ float  sm_m[16], sm_d[16], sm_scale[16];
    __shared__ __align__(16) float4 sm_r[16][128];

    int lo = 0, hi = B_GRAPHS;
    while (lo < hi) {
        int mid = (lo + hi) >> 1;
        if (g_off[mid + 1] <= i0) lo = mid + 1; else hi = mid;
    }
    int b = lo;

    while (b < B_GRAPHS && g_off[b] < i1) {
        const int s0 = max(g_off[b], i0);
        const int s1 = min(g_off[b + 1], i1);
        if (s1 > s0) {
            sm_q[tid] = g_hr[b * 1024 + tid];
            __syncthreads();
            const float4* q4 = (const float4*)sm_q;

            float m = -CUDART_INF_F, denom = 0.0f;
            float r[16];
            #pragma unroll
            for (int k = 0; k < 16; k++) r[k] = 0.0f;

            for (int n = s0 + wid; n < s1; n += 16) {
                const float4* xr = (const float4*)(x + (size_t)n * D_IN);
                float xv[16];
                #pragma unroll
                for (int j = 0; j < 4; j++) {
                    float4 v = __ldcs(xr + j * 32 + lane);
                    xv[j*4+0] = v.x; xv[j*4+1] = v.y;
                    xv[j*4+2] = v.z; xv[j*4+3] = v.w;
                }
                {
                    uint2* row16 = (uint2*)(g_x16 + (size_t)n * D_IN);
                    #pragma unroll
                    for (int j = 0; j < 4; j++) {
                        __half2 h0 = __floats2half2_rn(xv[j*4+0], xv[j*4+1]);
                        __half2 h1 = __floats2half2_rn(xv[j*4+2], xv[j*4+3]);
                        uint2 px;
                        px.x = *(unsigned*)&h0;
                        px.y = *(unsigned*)&h1;
                        row16[j * 32 + lane] = px;
                    }
                }

                float p = 0.0f;
                #pragma unroll
                for (int j = 0; j < 4; j++) {
                    float4 qv = q4[j * 32 + lane];
                    p = fmaf(xv[j*4+0], qv.x, p);
                    p = fmaf(xv[j*4+1], qv.y, p);
                    p = fmaf(xv[j*4+2], qv.z, p);
                    p = fmaf(xv[j*4+3], qv.w, p);
                }
                #pragma unroll
                for (int o = 16; o; o >>= 1) p += __shfl_xor_sync(0xffffffffu, p, o);

                const float mn = fmaxf(m, p);
                const float sc = __expf(m - mn);
                const float wg = __expf(p - mn);
                denom = fmaf(denom, sc, wg);
                #pragma unroll
                for (int k = 0; k < 16; k++) r[k] = fmaf(r[k], sc, wg * xv[k]);
                m = mn;
            }

            if (lane == 0) { sm_m[wid] = m; sm_d[wid] = denom; }
            #pragma unroll
            for (int j = 0; j < 4; j++)
                sm_r[wid][j * 32 + lane] =
                    make_float4(r[j*4+0], r[j*4+1], r[j*4+2], r[j*4+3]);
            __syncthreads();

            float M = -CUDART_INF_F;
            #pragma unroll
            for (int w = 0; w < 16; w++) M = fmaxf(M, sm_m[w]);
            if (tid < 16)
                sm_scale[tid] = (sm_m[tid] == -CUDART_INF_F) ? 0.0f : __expf(sm_m[tid] - M);
            __syncthreads();

            float Dn = 0.0f, num = 0.0f;
            #pragma unroll
            for (int w = 0; w < 16; w++) {
                Dn  += sm_d[w] * sm_scale[w];
                num  = fmaf(((const float*)sm_r[w])[tid], sm_scale[w], num);
            }

            const int slot = chunk - g_off[b] / CHUNK;
            g_part_r[(b * MAX_SLOTS + slot) * D_IN + tid] = num;
            if (tid == 0) {
                g_part_m[b * MAX_SLOTS + slot] = M;
                g_part_d[b * MAX_SLOTS + slot] = Dn;
            }
            __syncthreads();
        }
        b++;
    }
}

// ---------- attention steps 1..5: fp16 sweep, 2 nodes per warp-iter ----------
// Lane owns cols [8*lane, 8*lane+8) and [256+8*lane, 256+8*lane+8).
__global__ void __launch_bounds__(512, 2) attn16_kernel() {
    const int chunk = blockIdx.x;
    const int i0 = chunk * CHUNK;
    const int i1 = min(i0 + CHUNK, N_NODES);
    const int tid  = threadIdx.x;
    const int wid  = tid >> 5;
    const int lane = tid & 31;

    __shared__ __align__(16) float sm_q[D_IN];
    __shared__ float  sm_m[16], sm_d[16], sm_scale[16];
    __shared__ __align__(16) float4 sm_r[16][128];

    int lo = 0, hi = B_GRAPHS;
    while (lo < hi) {
        int mid = (lo + hi) >> 1;
        if (g_off[mid + 1] <= i0) lo = mid + 1; else hi = mid;
    }
    int b = lo;

    while (b < B_GRAPHS && g_off[b] < i1) {
        const int s0 = max(g_off[b], i0);
        const int s1 = min(g_off[b + 1], i1);
        if (s1 > s0) {
            sm_q[tid] = g_hr[b * 1024 + tid];
            __syncthreads();
            float qf[16];
            #pragma unroll
            for (int k = 0; k < 8; k++) qf[k]     = sm_q[8 * lane + k];
            #pragma unroll
            for (int k = 0; k < 8; k++) qf[8 + k] = sm_q[256 + 8 * lane + k];

            float m = -CUDART_INF_F, denom = 0.0f;
            float r[16];
            #pragma unroll
            for (int k = 0; k < 16; k++) r[k] = 0.0f;

            for (int n = s0 + wid * 2; n < s1; n += 32) {
                const uint4* rowa = (const uint4*)(g_x16 + (size_t)n * D_IN);
                uint4 a0 = __ldcs(rowa + lane);
                uint4 a1 = __ldcs(rowa + 32 + lane);
                const bool has_b = (n + 1) < s1;
                uint4 b0, b1;
                if (has_b) {
                    const uint4* rowb = (const uint4*)(g_x16 + (size_t)(n + 1) * D_IN);
                    b0 = __ldcs(rowb + lane);
                    b1 = __ldcs(rowb + 32 + lane);
                }

                float xf[16];
                {
                    const unsigned* u = (const unsigned*)&a0;
                    #pragma unroll
                    for (int t = 0; t < 4; t++) {
                        float2 f = __half22float2(*(const __half2*)&u[t]);
                        xf[t*2+0] = f.x; xf[t*2+1] = f.y;
                    }
                    const unsigned* v = (const unsigned*)&a1;
                    #pragma unroll
                    for (int t = 0; t < 4; t++) {
                        float2 f = __half22float2(*(const __half2*)&v[t]);
                        xf[8+t*2+0] = f.x; xf[8+t*2+1] = f.y;
                    }
                }
                float p = 0.0f;
                #pragma unroll
                for (int k = 0; k < 16; k++) p = fmaf(xf[k], qf[k], p);
                #pragma unroll
                for (int o = 16; o; o >>= 1) p += __shfl_xor_sync(0xffffffffu, p, o);
                float mn = fmaxf(m, p);
                float sc = __expf(m - mn);
                float wg = __expf(p - mn);
                denom = fmaf(denom, sc, wg);
                #pragma unroll
                for (int k = 0; k < 16; k++) r[k] = fmaf(r[k], sc, wg * xf[k]);
                m = mn;

                if (has_b) {
                    float yf[16];
                    {
                        const unsigned* u = (const unsigned*)&b0;
                        #pragma unroll
                        for (int t = 0; t < 4; t++) {
                            float2 f = __half22float2(*(const __half2*)&u[t]);
                            yf[t*2+0] = f.x; yf[t*2+1] = f.y;
                        }
                        const unsigned* v = (const unsigned*)&b1;
                        #pragma unroll
                        for (int t = 0; t < 4; t++) {
                            float2 f = __half22float2(*(const __half2*)&v[t]);
                            yf[8+t*2+0] = f.x; yf[8+t*2+1] = f.y;
                        }
                    }
                    float pb = 0.0f;
                    #pragma unroll
                    for (int k = 0; k < 16; k++) pb = fmaf(yf[k], qf[k], pb);
                    #pragma unroll
                    for (int o = 16; o; o >>= 1) pb += __shfl_xor_sync(0xffffffffu, pb, o);
                    mn = fmaxf(m, pb);
                    sc = __expf(m - mn);
                    wg = __expf(pb - mn);
                    denom = fmaf(denom, sc, wg);
                    #pragma unroll
                    for (int k = 0; k < 16; k++) r[k] = fmaf(r[k], sc, wg * yf[k]);
                    m = mn;
                }
            }

            if (lane == 0) { sm_m[wid] = m; sm_d[wid] = denom; }
            {
                float* dst = (float*)sm_r[wid];
                #pragma unroll
                for (int k = 0; k < 8; k++) dst[8 * lane + k]       = r[k];
                #pragma unroll
                for (int k = 0; k < 8; k++) dst[256 + 8 * lane + k] = r[8 + k];
            }
            __syncthreads();

            float M = -CUDART_INF_F;
            #pragma unroll
            for (int w = 0; w < 16; w++) M = fmaxf(M, sm_m[w]);
            if (tid < 16)
                sm_scale[tid] = (sm_m[tid] == -CUDART_INF_F) ? 0.0f : __expf(sm_m[tid] - M);
            __syncthreads();

            float Dn = 0.0f, num = 0.0f;
            #pragma unroll
            for (int w = 0; w < 16; w++) {
                Dn  += sm_d[w] * sm_scale[w];
                num  = fmaf(((const float*)sm_r[w])[tid], sm_scale[w], num);
            }

            const int slot = chunk - g_off[b] / CHUNK;
            g_part_r[(b * MAX_SLOTS + slot) * D_IN + tid] = num;
            if (tid == 0) {
                g_part_m[b * MAX_SLOTS + slot] = M;
                g_part_d[b * MAX_SLOTS + slot] = Dn;
            }
            __syncthreads();
        }
        b++;
    }
}

// ------------------ attention pass 2: per-graph merge ------------------------
// Writes r (fp32 + fp16); on the final step also writes q_star to out.
__global__ void attn_merge_kernel(float* __restrict__ out) {
    const int b   = blockIdx.x;
    const int tid = threadIdx.x;
    const int o0 = g_off[b], o1 = g_off[b + 1];
    float res = 0.0f;
    if (o1 > o0) {
        const int J = (o1 - 1) / CHUNK - o0 / CHUNK + 1;
        float M = -CUDART_INF_F;
        for (int j = 0; j < J; j++) M = fmaxf(M, g_part_m[b * MAX_SLOTS + j]);
        float D = 0.0f, acc = 0.0f;
        for (int j = 0; j < J; j++) {
            const float s = __expf(g_part_m[b * MAX_SLOTS + j] - M);
            D   = fmaf(g_part_d[b * MAX_SLOTS + j], s, D);
            acc = fmaf(g_part_r[(b * MAX_SLOTS + j) * D_IN + tid], s, acc);
        }
        res = acc / (D + 1e-16f);
    }
    g_hr[b * 1024 + 512 + tid] = res;
    g_hr16[b * 1024 + 512 + tid] = __float2half_rn(res);
    if (out) {
        out[b * 1024 + tid]       = g_hr[b * 1024 + tid];   // h half
        out[b * 1024 + 512 + tid] = res;                    // r half
    }
}

// ------------------------------- launch --------------------------------------
extern "C" void kernel_launch(void* const* d_in, const int* in_sizes, int n_in,
                              void* d_out, int out_size) {
    const float* x     = (const float*)d_in[0];
    const int*   batch = (const int*)d_in[1];
    const float* w_ih  = (const float*)d_in[2];
    const float* w_hh  = (const float*)d_in[3];
    const float* b_ih  = (const float*)d_in[4];
    const float* b_hh  = (const float*)d_in[5];
    float* out = (float*)d_out;

    prep_w_kernel<<<(GATES * K_COMB) / 256, 256>>>(w_ih, w_hh, b_ih, b_hh);
    offsets_kernel<<<2, 160>>>(batch);
    lstm_init_kernel<<<B_GRAPHS, 512>>>();

    for (int s = 0; s < STEPS; s++) {
        if (s > 0)
            gemm_lstm_kernel<<<dim3(16, 4), 256>>>();
        if (s == 0)
            attn0_kernel<<<N_CHUNKS, 512>>>(x);
        else
            attn16_kernel<<<N_CHUNKS, 512>>>();
        attn_merge_kernel<<<B_GRAPHS, 512>>>(s == STEPS - 1 ? out : nullptr);
    }
}

// round 13
// speedup vs baseline: 1.0935x; 1.0935x over previous
#include <cuda_runtime.h>
#include <cuda_fp16.h>
#include <math_constants.h>
#include <mma.h>

using namespace nvcuda;

#define N_NODES   262144
#define D_IN      512
#define B_GRAPHS  256
#define GATES     2048      // 4*D_IN
#define K_COMB    1024      // combined K (h:512 | r:512)
#define STEPS     6

// ----------------- device scratch (no runtime allocation allowed) -----------
__device__ __align__(16) __half g_W16[GATES * K_COMB];    // fp16 combined weights (4 MB)
__device__ __align__(16) float  g_bias[GATES];
__device__ __align__(16) float  g_hr[B_GRAPHS * 1024];    // [h | r] = q_star (fp32)
__device__ __align__(16) __half g_hr16[B_GRAPHS * 1024];  // fp16 copy for GEMM
__device__ __align__(16) float  g_c[B_GRAPHS * D_IN];
__device__ __align__(16) float  g_gates[B_GRAPHS * GATES];
__device__ __align__(16) __half g_x16[(size_t)N_NODES * D_IN];  // 256 MB fp16 copy
__device__ int g_off[B_GRAPHS + 1];

// ----------------------------- helpers --------------------------------------
__device__ __forceinline__ float sigm(float v) {
    return 1.0f / (1.0f + __expf(-v));
}

// --------------------------- prep kernels -----------------------------------
__global__ void prep_w_kernel(const float* __restrict__ w_ih,
                              const float* __restrict__ w_hh,
                              const float* __restrict__ b_ih,
                              const float* __restrict__ b_hh) {
    int idx = blockIdx.x * blockDim.x + threadIdx.x;
    int n = idx >> 10;
    int k = idx & 1023;
    float v = w_ih[n * 1024 + k];
    if (k < 512) v += w_hh[n * 512 + k];
    g_W16[idx] = __float2half_rn(v);
    if (idx < GATES) g_bias[idx] = b_ih[idx] + b_hh[idx];
}

__global__ void offsets_kernel(const int* __restrict__ batch) {
    int t = blockIdx.x * blockDim.x + threadIdx.x;
    if (t > B_GRAPHS) return;
    int lo = 0, hi = N_NODES;
    while (lo < hi) {
        int mid = (lo + hi) >> 1;
        if (batch[mid] < t) lo = mid + 1; else hi = mid;
    }
    g_off[t] = lo;
}

// Step 0: q_star = 0, h = 0 -> gates = bias (identical for every graph)
__global__ void lstm_init_kernel() {
    int b = blockIdx.x;
    int d = threadIdx.x;
    float i = sigm(g_bias[d]);
    float g = tanhf(g_bias[1024 + d]);
    float o = sigm(g_bias[1536 + d]);
    float c = i * g;
    float h = o * tanhf(c);
    g_c[b * D_IN + d]  = c;
    g_hr[b * 1024 + d] = h;
    g_hr16[b * 1024 + d] = __float2half_rn(h);
}

// ------------- GEMM (fp16 HMMA, fp32 accum): gates = hr @ W^T ----------------
// M=256, N=2048, K=1024. CTA tile 64x64, 8 warps, warp = 1x2 m16n16k16 tiles.
__global__ void __launch_bounds__(256) gemm_tc_kernel() {
    __shared__ __align__(16) __half sA[64][40];
    __shared__ __align__(16) __half sB[64][40];

    const int bm = blockIdx.y * 64;        // gridDim.y = 4
    const int bn = blockIdx.x * 64;        // gridDim.x = 32
    const int tid = threadIdx.x;
    const int w   = tid >> 5;
    const int mt  = w & 3;
    const int ng  = w >> 2;

    wmma::fragment<wmma::accumulator, 16, 16, 16, float> cf[2];
    wmma::fill_fragment(cf[0], 0.0f);
    wmma::fill_fragment(cf[1], 0.0f);

    const int row = tid >> 2;              // 0..63
    const int col = (tid & 3) * 8;         // halves: 0,8,16,24

    const __half* Ag = g_hr16 + (bm + row) * K_COMB + col;
    const __half* Bg = g_W16  + (bn + row) * K_COMB + col;

    uint4 a = *(const uint4*)(Ag);
    uint4 bvec = *(const uint4*)(Bg);

    for (int k0 = 0; k0 < K_COMB; k0 += 32) {
        *(uint4*)&sA[row][col] = a;
        *(uint4*)&sB[row][col] = bvec;
        __syncthreads();

        if (k0 + 32 < K_COMB) {
            a    = *(const uint4*)(Ag + k0 + 32);
            bvec = *(const uint4*)(Bg + k0 + 32);
        }

        #pragma unroll
        for (int kk = 0; kk < 32; kk += 16) {
            wmma::fragment<wmma::matrix_a, 16, 16, 16, __half, wmma::row_major> af;
            wmma::load_matrix_sync(af, &sA[mt * 16][kk], 40);
            #pragma unroll
            for (int t = 0; t < 2; t++) {
                wmma::fragment<wmma::matrix_b, 16, 16, 16, __half, wmma::col_major> bf;
                wmma::load_matrix_sync(bf, &sB[(ng * 2 + t) * 16][kk], 40);
                wmma::mma_sync(cf[t], af, bf, cf[t]);
            }
        }
        __syncthreads();
    }

    #pragma unroll
    for (int t = 0; t < 2; t++)
        wmma::store_matrix_sync(&g_gates[(bm + mt * 16) * GATES + bn + (ng * 2 + t) * 16],
                                cf[t], GATES, wmma::mem_row_major);
}

// --------------------------- LSTM pointwise (adds bias) ----------------------
__global__ void lstm_pw_kernel() {
    int idx = blockIdx.x * blockDim.x + threadIdx.x;
    int b = idx >> 9;
    int d = idx & 511;
    const float* gr = g_gates + b * GATES + d;
    float i = sigm(gr[0]    + g_bias[d]);
    float f = sigm(gr[512]  + g_bias[512 + d]);
    float g = tanhf(gr[1024] + g_bias[1024 + d]);
    float o = sigm(gr[1536] + g_bias[1536 + d]);
    float c = f * g_c[idx] + i * g;
    g_c[idx] = c;
    float h = o * tanhf(c);
    g_hr[b * 1024 + d] = h;                       // q = h into hr[:, :512]
    g_hr16[b * 1024 + d] = __float2half_rn(h);
}

// ---------- attention step 0: one block per graph, fp32 + fp16 copy ----------
// Warp-per-node online softmax; col layout slot j*4+c <-> column 128*j+4*lane+c.
// Block-level reduction yields FINAL r -> written directly (no merge kernel).
__global__ void __launch_bounds__(512, 2) attn0_kernel(const float* __restrict__ x) {
    const int b    = blockIdx.x;
    const int tid  = threadIdx.x;
    const int wid  = tid >> 5;
    const int lane = tid & 31;

    const int s0 = g_off[b];
    const int s1 = g_off[b + 1];

    __shared__ __align__(16) float sm_q[D_IN];
    __shared__ float  sm_m[16], sm_d[16], sm_scale[16];
    __shared__ __align__(16) float4 sm_r[16][128];

    sm_q[tid] = g_hr[b * 1024 + tid];
    __syncthreads();
    const float4* q4 = (const float4*)sm_q;

    float m = -CUDART_INF_F, denom = 0.0f;
    float r[16];
    #pragma unroll
    for (int k = 0; k < 16; k++) r[k] = 0.0f;

    for (int n = s0 + wid; n < s1; n += 16) {
        const float4* xr = (const float4*)(x + (size_t)n * D_IN);
        float xv[16];
        #pragma unroll
        for (int j = 0; j < 4; j++) {
            float4 v = __ldcs(xr + j * 32 + lane);
            xv[j*4+0] = v.x; xv[j*4+1] = v.y;
            xv[j*4+2] = v.z; xv[j*4+3] = v.w;
        }
        {
            uint2* row16 = (uint2*)(g_x16 + (size_t)n * D_IN);
            #pragma unroll
            for (int j = 0; j < 4; j++) {
                __half2 h0 = __floats2half2_rn(xv[j*4+0], xv[j*4+1]);
                __half2 h1 = __floats2half2_rn(xv[j*4+2], xv[j*4+3]);
                uint2 px;
                px.x = *(unsigned*)&h0;
                px.y = *(unsigned*)&h1;
                row16[j * 32 + lane] = px;
            }
        }

        float p = 0.0f;
        #pragma unroll
        for (int j = 0; j < 4; j++) {
            float4 qv = q4[j * 32 + lane];
            p = fmaf(xv[j*4+0], qv.x, p);
            p = fmaf(xv[j*4+1], qv.y, p);
            p = fmaf(xv[j*4+2], qv.z, p);
            p = fmaf(xv[j*4+3], qv.w, p);
        }
        #pragma unroll
        for (int o = 16; o; o >>= 1) p += __shfl_xor_sync(0xffffffffu, p, o);

        const float mn = fmaxf(m, p);
        const float sc = __expf(m - mn);
        const float wg = __expf(p - mn);
        denom = fmaf(denom, sc, wg);
        #pragma unroll
        for (int k = 0; k < 16; k++) r[k] = fmaf(r[k], sc, wg * xv[k]);
        m = mn;
    }

    if (lane == 0) { sm_m[wid] = m; sm_d[wid] = denom; }
    #pragma unroll
    for (int j = 0; j < 4; j++)
        sm_r[wid][j * 32 + lane] =
            make_float4(r[j*4+0], r[j*4+1], r[j*4+2], r[j*4+3]);
    __syncthreads();

    float M = -CUDART_INF_F;
    #pragma unroll
    for (int w = 0; w < 16; w++) M = fmaxf(M, sm_m[w]);
    if (tid < 16)
        sm_scale[tid] = (sm_m[tid] == -CUDART_INF_F) ? 0.0f : __expf(sm_m[tid] - M);
    __syncthreads();

    float Dn = 0.0f, num = 0.0f;
    #pragma unroll
    for (int w = 0; w < 16; w++) {
        Dn  += sm_d[w] * sm_scale[w];
        num  = fmaf(((const float*)sm_r[w])[tid], sm_scale[w], num);
    }
    const float res = num / (Dn + 1e-16f);
    g_hr[b * 1024 + 512 + tid] = res;
    g_hr16[b * 1024 + 512 + tid] = __float2half_rn(res);
}

// ------- attention steps 1..5: one block per graph, fp16, direct r write -----
// Lane owns cols [8*lane, 8*lane+8) and [256+8*lane, 256+8*lane+8).
// On the final step also writes q_star = [h | r] to out.
__global__ void __launch_bounds__(512, 2) attn16_kernel(float* __restrict__ out) {
    const int b    = blockIdx.x;
    const int tid  = threadIdx.x;
    const int wid  = tid >> 5;
    const int lane = tid & 31;

    const int s0 = g_off[b];
    const int s1 = g_off[b + 1];

    __shared__ __align__(16) float sm_q[D_IN];
    __shared__ float  sm_m[16], sm_d[16], sm_scale[16];
    __shared__ __align__(16) float4 sm_r[16][128];

    sm_q[tid] = g_hr[b * 1024 + tid];
    __syncthreads();
    float qf[16];
    #pragma unroll
    for (int k = 0; k < 8; k++) qf[k]     = sm_q[8 * lane + k];
    #pragma unroll
    for (int k = 0; k < 8; k++) qf[8 + k] = sm_q[256 + 8 * lane + k];

    float m = -CUDART_INF_F, denom = 0.0f;
    float r[16];
    #pragma unroll
    for (int k = 0; k < 16; k++) r[k] = 0.0f;

    for (int n = s0 + wid * 2; n < s1; n += 32) {
        const uint4* rowa = (const uint4*)(g_x16 + (size_t)n * D_IN);
        uint4 a0 = __ldcs(rowa + lane);
        uint4 a1 = __ldcs(rowa + 32 + lane);
        const bool has_b = (n + 1) < s1;
        uint4 b0, b1;
        if (has_b) {
            const uint4* rowb = (const uint4*)(g_x16 + (size_t)(n + 1) * D_IN);
            b0 = __ldcs(rowb + lane);
            b1 = __ldcs(rowb + 32 + lane);
        }

        float xf[16];
        {
            const unsigned* u = (const unsigned*)&a0;
            #pragma unroll
            for (int t = 0; t < 4; t++) {
                float2 f = __half22float2(*(const __half2*)&u[t]);
                xf[t*2+0] = f.x; xf[t*2+1] = f.y;
            }
            const unsigned* v = (const unsigned*)&a1;
            #pragma unroll
            for (int t = 0; t < 4; t++) {
                float2 f = __half22float2(*(const __half2*)&v[t]);
                xf[8+t*2+0] = f.x; xf[8+t*2+1] = f.y;
            }
        }
        float p = 0.0f;
        #pragma unroll
        for (int k = 0; k < 16; k++) p = fmaf(xf[k], qf[k], p);
        #pragma unroll
        for (int o = 16; o; o >>= 1) p += __shfl_xor_sync(0xffffffffu, p, o);
        float mn = fmaxf(m, p);
        float sc = __expf(m - mn);
        float wg = __expf(p - mn);
        denom = fmaf(denom, sc, wg);
        #pragma unroll
        for (int k = 0; k < 16; k++) r[k] = fmaf(r[k], sc, wg * xf[k]);
        m = mn;

        if (has_b) {
            float yf[16];
            {
                const unsigned* u = (const unsigned*)&b0;
                #pragma unroll
                for (int t = 0; t < 4; t++) {
                    float2 f = __half22float2(*(const __half2*)&u[t]);
                    yf[t*2+0] = f.x; yf[t*2+1] = f.y;
                }
                const unsigned* v = (const unsigned*)&b1;
                #pragma unroll
                for (int t = 0; t < 4; t++) {
                    float2 f = __half22float2(*(const __half2*)&v[t]);
                    yf[8+t*2+0] = f.x; yf[8+t*2+1] = f.y;
                }
            }
            float pb = 0.0f;
            #pragma unroll
            for (int k = 0; k < 16; k++) pb = fmaf(yf[k], qf[k], pb);
            #pragma unroll
            for (int o = 16; o; o >>= 1) pb += __shfl_xor_sync(0xffffffffu, pb, o);
            mn = fmaxf(m, pb);
            sc = __expf(m - mn);
            wg = __expf(pb - mn);
            denom = fmaf(denom, sc, wg);
            #pragma unroll
            for (int k = 0; k < 16; k++) r[k] = fmaf(r[k], sc, wg * yf[k]);
            m = mn;
        }
    }

    if (lane == 0) { sm_m[wid] = m; sm_d[wid] = denom; }
    {
        float* dst = (float*)sm_r[wid];
        #pragma unroll
        for (int k = 0; k < 8; k++) dst[8 * lane + k]       = r[k];
        #pragma unroll
        for (int k = 0; k < 8; k++) dst[256 + 8 * lane + k] = r[8 + k];
    }
    __syncthreads();

    float M = -CUDART_INF_F;
    #pragma unroll
    for (int w = 0; w < 16; w++) M = fmaxf(M, sm_m[w]);
    if (tid < 16)
        sm_scale[tid] = (sm_m[tid] == -CUDART_INF_F) ? 0.0f : __expf(sm_m[tid] - M);
    __syncthreads();

    float Dn = 0.0f, num = 0.0f;
    #pragma unroll
    for (int w = 0; w < 16; w++) {
        Dn  += sm_d[w] * sm_scale[w];
        num  = fmaf(((const float*)sm_r[w])[tid], sm_scale[w], num);
    }
    const float res = num / (Dn + 1e-16f);
    g_hr[b * 1024 + 512 + tid] = res;
    g_hr16[b * 1024 + 512 + tid] = __float2half_rn(res);
    if (out) {
        out[b * 1024 + tid]       = sm_q[tid];   // h half (== q this step)
        out[b * 1024 + 512 + tid] = res;         // r half
    }
}

// ------------------------------- launch --------------------------------------
extern "C" void kernel_launch(void* const* d_in, const int* in_sizes, int n_in,
                              void* d_out, int out_size) {
    const float* x     = (const float*)d_in[0];
    const int*   batch = (const int*)d_in[1];
    const float* w_ih  = (const float*)d_in[2];
    const float* w_hh  = (const float*)d_in[3];
    const float* b_ih  = (const float*)d_in[4];
    const float* b_hh  = (const float*)d_in[5];
    float* out = (float*)d_out;

    prep_w_kernel<<<(GATES * K_COMB) / 256, 256>>>(w_ih, w_hh, b_ih, b_hh);
    offsets_kernel<<<2, 160>>>(batch);
    lstm_init_kernel<<<B_GRAPHS, 512>>>();

    for (int s = 0; s < STEPS; s++) {
        if (s > 0) {
            gemm_tc_kernel<<<dim3(32, 4), 256>>>();
            lstm_pw_kernel<<<(B_GRAPHS * D_IN) / 512, 512>>>();
        }
        if (s == 0)
            attn0_kernel<<<B_GRAPHS, 512>>>(x);
        else
            attn16_kernel<<<B_GRAPHS, 512>>>(s == STEPS - 1 ? out : nullptr);
    }
}

// round 14
// speedup vs baseline: 1.1212x; 1.0254x over previous
#include <cuda_runtime.h>
#include <cuda_fp16.h>
#include <math_constants.h>
#include <mma.h>

using namespace nvcuda;

#define N_NODES   262144
#define D_IN      512
#define B_GRAPHS  256
#define GATES     2048      // 4*D_IN
#define K_COMB    1024      // combined K (h:512 | r:512)
#define STEPS     6

// ----------------- device scratch (no runtime allocation allowed) -----------
__device__ __align__(16) __half g_W16[GATES * K_COMB];    // fp16 combined weights (4 MB)
__device__ __align__(16) float  g_bias[GATES];
__device__ __align__(16) float  g_hr[B_GRAPHS * 1024];    // fp32 q_star (attn0 only)
__device__ __align__(16) __half g_hr16[B_GRAPHS * 1024];  // fp16 [h | r] for GEMM
__device__ __align__(16) float  g_c[B_GRAPHS * D_IN];
__device__ __align__(16) float  g_gates[B_GRAPHS * GATES];
__device__ __align__(16) __half g_x16[(size_t)N_NODES * D_IN];  // 256 MB fp16 copy
__device__ int g_off[B_GRAPHS + 1];

// ----------------------------- helpers --------------------------------------
__device__ __forceinline__ float sigm(float v) {
    return 1.0f / (1.0f + __expf(-v));
}

// --------------------------- prep kernels -----------------------------------
__global__ void prep_w_kernel(const float* __restrict__ w_ih,
                              const float* __restrict__ w_hh,
                              const float* __restrict__ b_ih,
                              const float* __restrict__ b_hh) {
    int idx = blockIdx.x * blockDim.x + threadIdx.x;
    int n = idx >> 10;
    int k = idx & 1023;
    float v = w_ih[n * 1024 + k];
    if (k < 512) v += w_hh[n * 512 + k];
    g_W16[idx] = __float2half_rn(v);
    if (idx < GATES) g_bias[idx] = b_ih[idx] + b_hh[idx];
}

__global__ void offsets_kernel(const int* __restrict__ batch) {
    int t = blockIdx.x * blockDim.x + threadIdx.x;
    if (t > B_GRAPHS) return;
    int lo = 0, hi = N_NODES;
    while (lo < hi) {
        int mid = (lo + hi) >> 1;
        if (batch[mid] < t) lo = mid + 1; else hi = mid;
    }
    g_off[t] = lo;
}

// Step 0: q_star = 0, h = 0 -> gates = bias (identical for every graph)
__global__ void lstm_init_kernel() {
    int b = blockIdx.x;
    int d = threadIdx.x;
    float i = sigm(g_bias[d]);
    float g = tanhf(g_bias[1024 + d]);
    float o = sigm(g_bias[1536 + d]);
    float c = i * g;
    float h = o * tanhf(c);
    g_c[b * D_IN + d]  = c;
    g_hr[b * 1024 + d] = h;
    g_hr16[b * 1024 + d] = __float2half_rn(h);
}

// ------------- GEMM (fp16 HMMA, fp32 accum): gates = hr @ W^T ----------------
// M=256, N=2048, K=1024. CTA tile 64x64, 8 warps, warp = 1x2 m16n16k16 tiles.
__global__ void __launch_bounds__(256) gemm_tc_kernel() {
    __shared__ __align__(16) __half sA[64][40];
    __shared__ __align__(16) __half sB[64][40];

    const int bm = blockIdx.y * 64;        // gridDim.y = 4
    const int bn = blockIdx.x * 64;        // gridDim.x = 32
    const int tid = threadIdx.x;
    const int w   = tid >> 5;
    const int mt  = w & 3;
    const int ng  = w >> 2;

    wmma::fragment<wmma::accumulator, 16, 16, 16, float> cf[2];
    wmma::fill_fragment(cf[0], 0.0f);
    wmma::fill_fragment(cf[1], 0.0f);

    const int row = tid >> 2;              // 0..63
    const int col = (tid & 3) * 8;         // halves: 0,8,16,24

    const __half* Ag = g_hr16 + (bm + row) * K_COMB + col;
    const __half* Bg = g_W16  + (bn + row) * K_COMB + col;

    uint4 a = *(const uint4*)(Ag);
    uint4 bvec = *(const uint4*)(Bg);

    for (int k0 = 0; k0 < K_COMB; k0 += 32) {
        *(uint4*)&sA[row][col] = a;
        *(uint4*)&sB[row][col] = bvec;
        __syncthreads();

        if (k0 + 32 < K_COMB) {
            a    = *(const uint4*)(Ag + k0 + 32);
            bvec = *(const uint4*)(Bg + k0 + 32);
        }

        #pragma unroll
        for (int kk = 0; kk < 32; kk += 16) {
            wmma::fragment<wmma::matrix_a, 16, 16, 16, __half, wmma::row_major> af;
            wmma::load_matrix_sync(af, &sA[mt * 16][kk], 40);
            #pragma unroll
            for (int t = 0; t < 2; t++) {
                wmma::fragment<wmma::matrix_b, 16, 16, 16, __half, wmma::col_major> bf;
                wmma::load_matrix_sync(bf, &sB[(ng * 2 + t) * 16][kk], 40);
                wmma::mma_sync(cf[t], af, bf, cf[t]);
            }
        }
        __syncthreads();
    }

    #pragma unroll
    for (int t = 0; t < 2; t++)
        wmma::store_matrix_sync(&g_gates[(bm + mt * 16) * GATES + bn + (ng * 2 + t) * 16],
                                cf[t], GATES, wmma::mem_row_major);
}

// ---------- attention step 0: one block per graph, fp32 + fp16 copy ----------
// Warp-per-node online softmax; col layout slot j*4+c <-> column 128*j+4*lane+c.
__global__ void __launch_bounds__(512, 2) attn0_kernel(const float* __restrict__ x) {
    const int b    = blockIdx.x;
    const int tid  = threadIdx.x;
    const int wid  = tid >> 5;
    const int lane = tid & 31;

    const int s0 = g_off[b];
    const int s1 = g_off[b + 1];

    __shared__ __align__(16) float sm_q[D_IN];
    __shared__ float  sm_m[16], sm_d[16], sm_scale[16];
    __shared__ __align__(16) float4 sm_r[16][128];

    sm_q[tid] = g_hr[b * 1024 + tid];
    __syncthreads();
    const float4* q4 = (const float4*)sm_q;

    float m = -CUDART_INF_F, denom = 0.0f;
    float r[16];
    #pragma unroll
    for (int k = 0; k < 16; k++) r[k] = 0.0f;

    for (int n = s0 + wid; n < s1; n += 16) {
        const float4* xr = (const float4*)(x + (size_t)n * D_IN);
        float xv[16];
        #pragma unroll
        for (int j = 0; j < 4; j++) {
            float4 v = __ldcs(xr + j * 32 + lane);
            xv[j*4+0] = v.x; xv[j*4+1] = v.y;
            xv[j*4+2] = v.z; xv[j*4+3] = v.w;
        }
        {
            uint2* row16 = (uint2*)(g_x16 + (size_t)n * D_IN);
            #pragma unroll
            for (int j = 0; j < 4; j++) {
                __half2 h0 = __floats2half2_rn(xv[j*4+0], xv[j*4+1]);
                __half2 h1 = __floats2half2_rn(xv[j*4+2], xv[j*4+3]);
                uint2 px;
                px.x = *(unsigned*)&h0;
                px.y = *(unsigned*)&h1;
                row16[j * 32 + lane] = px;
            }
        }

        float p = 0.0f;
        #pragma unroll
        for (int j = 0; j < 4; j++) {
            float4 qv = q4[j * 32 + lane];
            p = fmaf(xv[j*4+0], qv.x, p);
            p = fmaf(xv[j*4+1], qv.y, p);
            p = fmaf(xv[j*4+2], qv.z, p);
            p = fmaf(xv[j*4+3], qv.w, p);
        }
        #pragma unroll
        for (int o = 16; o; o >>= 1) p += __shfl_xor_sync(0xffffffffu, p, o);

        const float mn = fmaxf(m, p);
        const float sc = __expf(m - mn);
        const float wg = __expf(p - mn);
        denom = fmaf(denom, sc, wg);
        #pragma unroll
        for (int k = 0; k < 16; k++) r[k] = fmaf(r[k], sc, wg * xv[k]);
        m = mn;
    }

    if (lane == 0) { sm_m[wid] = m; sm_d[wid] = denom; }
    #pragma unroll
    for (int j = 0; j < 4; j++)
        sm_r[wid][j * 32 + lane] =
            make_float4(r[j*4+0], r[j*4+1], r[j*4+2], r[j*4+3]);
    __syncthreads();

    float M = -CUDART_INF_F;
    #pragma unroll
    for (int w = 0; w < 16; w++) M = fmaxf(M, sm_m[w]);
    if (tid < 16)
        sm_scale[tid] = (sm_m[tid] == -CUDART_INF_F) ? 0.0f : __expf(sm_m[tid] - M);
    __syncthreads();

    float Dn = 0.0f, num = 0.0f;
    #pragma unroll
    for (int w = 0; w < 16; w++) {
        Dn  += sm_d[w] * sm_scale[w];
        num  = fmaf(((const float*)sm_r[w])[tid], sm_scale[w], num);
    }
    const float res = num / (Dn + 1e-16f);
    g_hr16[b * 1024 + 512 + tid] = __float2half_rn(res);
}

// ------- attention steps 1..5: LSTM-cell preamble + fp16 sweep ---------------
// Preamble: 512 threads compute h[b] = lstm(gates[b], c[b]) in-place (block b
// exclusively owns graph b -> no races), h -> sm_q + g_hr16 (next GEMM).
// Main: lane owns cols [8*lane,+8) and [256+8*lane,+8). Final step writes out.
__global__ void __launch_bounds__(512, 2) attn16_kernel(float* __restrict__ out) {
    const int b    = blockIdx.x;
    const int tid  = threadIdx.x;
    const int wid  = tid >> 5;
    const int lane = tid & 31;

    const int s0 = g_off[b];
    const int s1 = g_off[b + 1];

    __shared__ __align__(16) float sm_q[D_IN];
    __shared__ float  sm_m[16], sm_d[16], sm_scale[16];
    __shared__ __align__(16) float4 sm_r[16][128];

    // ---- LSTM cell preamble: one element per thread ----
    {
        const float* gr = g_gates + b * GATES + tid;
        const float i = sigm(gr[0]     + g_bias[tid]);
        const float f = sigm(gr[512]   + g_bias[512 + tid]);
        const float g = tanhf(gr[1024] + g_bias[1024 + tid]);
        const float o = sigm(gr[1536]  + g_bias[1536 + tid]);
        const int cidx = b * D_IN + tid;
        const float c = f * g_c[cidx] + i * g;
        g_c[cidx] = c;
        const float h = o * tanhf(c);
        sm_q[tid] = h;
        g_hr16[b * 1024 + tid] = __float2half_rn(h);   // for next step's GEMM
    }
    __syncthreads();

    float qf[16];
    #pragma unroll
    for (int k = 0; k < 8; k++) qf[k]     = sm_q[8 * lane + k];
    #pragma unroll
    for (int k = 0; k < 8; k++) qf[8 + k] = sm_q[256 + 8 * lane + k];

    float m = -CUDART_INF_F, denom = 0.0f;
    float r[16];
    #pragma unroll
    for (int k = 0; k < 16; k++) r[k] = 0.0f;

    for (int n = s0 + wid * 2; n < s1; n += 32) {
        const uint4* rowa = (const uint4*)(g_x16 + (size_t)n * D_IN);
        uint4 a0 = __ldcs(rowa + lane);
        uint4 a1 = __ldcs(rowa + 32 + lane);
        const bool has_b = (n + 1) < s1;
        uint4 b0, b1;
        if (has_b) {
            const uint4* rowb = (const uint4*)(g_x16 + (size_t)(n + 1) * D_IN);
            b0 = __ldcs(rowb + lane);
            b1 = __ldcs(rowb + 32 + lane);
        }

        float xf[16];
        {
            const unsigned* u = (const unsigned*)&a0;
            #pragma unroll
            for (int t = 0; t < 4; t++) {
                float2 f = __half22float2(*(const __half2*)&u[t]);
                xf[t*2+0] = f.x; xf[t*2+1] = f.y;
            }
            const unsigned* v = (const unsigned*)&a1;
            #pragma unroll
            for (int t = 0; t < 4; t++) {
                float2 f = __half22float2(*(const __half2*)&v[t]);
                xf[8+t*2+0] = f.x; xf[8+t*2+1] = f.y;
            }
        }
        float p = 0.0f;
        #pragma unroll
        for (int k = 0; k < 16; k++) p = fmaf(xf[k], qf[k], p);
        #pragma unroll
        for (int o = 16; o; o >>= 1) p += __shfl_xor_sync(0xffffffffu, p, o);
        float mn = fmaxf(m, p);
        float sc = __expf(m - mn);
        float wg = __expf(p - mn);
        denom = fmaf(denom, sc, wg);
        #pragma unroll
        for (int k = 0; k < 16; k++) r[k] = fmaf(r[k], sc, wg * xf[k]);
        m = mn;

        if (has_b) {
            float yf[16];
            {
                const unsigned* u = (const unsigned*)&b0;
                #pragma unroll
                for (int t = 0; t < 4; t++) {
                    float2 f = __half22float2(*(const __half2*)&u[t]);
                    yf[t*2+0] = f.x; yf[t*2+1] = f.y;
                }
                const unsigned* v = (const unsigned*)&b1;
                #pragma unroll
                for (int t = 0; t < 4; t++) {
                    float2 f = __half22float2(*(const __half2*)&v[t]);
                    yf[8+t*2+0] = f.x; yf[8+t*2+1] = f.y;
                }
            }
            float pb = 0.0f;
            #pragma unroll
            for (int k = 0; k < 16; k++) pb = fmaf(yf[k], qf[k], pb);
            #pragma unroll
            for (int o = 16; o; o >>= 1) pb += __shfl_xor_sync(0xffffffffu, pb, o);
            mn = fmaxf(m, pb);
            sc = __expf(m - mn);
            wg = __expf(pb - mn);
            denom = fmaf(denom, sc, wg);
            #pragma unroll
            for (int k = 0; k < 16; k++) r[k] = fmaf(r[k], sc, wg * yf[k]);
            m = mn;
        }
    }

    if (lane == 0) { sm_m[wid] = m; sm_d[wid] = denom; }
    {
        float* dst = (float*)sm_r[wid];
        #pragma unroll
        for (int k = 0; k < 8; k++) dst[8 * lane + k]       = r[k];
        #pragma unroll
        for (int k = 0; k < 8; k++) dst[256 + 8 * lane + k] = r[8 + k];
    }
    __syncthreads();

    float M = -CUDART_INF_F;
    #pragma unroll
    for (int w = 0; w < 16; w++) M = fmaxf(M, sm_m[w]);
    if (tid < 16)
        sm_scale[tid] = (sm_m[tid] == -CUDART_INF_F) ? 0.0f : __expf(sm_m[tid] - M);
    __syncthreads();

    float Dn = 0.0f, num = 0.0f;
    #pragma unroll
    for (int w = 0; w < 16; w++) {
        Dn  += sm_d[w] * sm_scale[w];
        num  = fmaf(((const float*)sm_r[w])[tid], sm_scale[w], num);
    }
    const float res = num / (Dn + 1e-16f);
    g_hr16[b * 1024 + 512 + tid] = __float2half_rn(res);
    if (out) {
        out[b * 1024 + tid]       = sm_q[tid];   // h half (== q this step)
        out[b * 1024 + 512 + tid] = res;         // r half
    }
}

// ------------------------------- launch --------------------------------------
extern "C" void kernel_launch(void* const* d_in, const int* in_sizes, int n_in,
                              void* d_out, int out_size) {
    const float* x     = (const float*)d_in[0];
    const int*   batch = (const int*)d_in[1];
    const float* w_ih  = (const float*)d_in[2];
    const float* w_hh  = (const float*)d_in[3];
    const float* b_ih  = (const float*)d_in[4];
    const float* b_hh  = (const float*)d_in[5];
    float* out = (float*)d_out;

    prep_w_kernel<<<(GATES * K_COMB) / 256, 256>>>(w_ih, w_hh, b_ih, b_hh);
    offsets_kernel<<<2, 160>>>(batch);
    lstm_init_kernel<<<B_GRAPHS, 512>>>();

    for (int s = 0; s < STEPS; s++) {
        if (s > 0)
            gemm_tc_kernel<<<dim3(32, 4), 256>>>();
        if (s == 0)
            attn0_kernel<<<B_GRAPHS, 512>>>(x);
        else
            attn16_kernel<<<B_GRAPHS, 512>>>(s == STEPS - 1 ? out : nullptr);
    }
}

// round 15
// speedup vs baseline: 1.2006x; 1.0708x over previous
#include <cuda_runtime.h>
#include <cuda_fp16.h>
#include <math_constants.h>
#include <mma.h>

using namespace nvcuda;

#define N_NODES   262144
#define D_IN      512
#define B_GRAPHS  256
#define GATES     2048      // 4*D_IN
#define K_COMB    1024      // combined K (h:512 | r:512)
#define STEPS     6
#define GSTAGES   4
#define KITERS    (K_COMB / 32)   // 32

// ----------------- device scratch (no runtime allocation allowed) -----------
__device__ __align__(16) __half g_W16[GATES * K_COMB];    // fp16 combined weights (4 MB)
__device__ __align__(16) float  g_bias[GATES];
__device__ __align__(16) float  g_hr[B_GRAPHS * 1024];    // fp32 q_star (attn0 only)
__device__ __align__(16) __half g_hr16[B_GRAPHS * 1024];  // fp16 [h | r] for GEMM
__device__ __align__(16) float  g_c[B_GRAPHS * D_IN];
__device__ __align__(16) float  g_gates[B_GRAPHS * GATES];
__device__ __align__(16) __half g_x16[(size_t)N_NODES * D_IN];  // 256 MB fp16 copy
__device__ int g_off[B_GRAPHS + 1];

// ----------------------------- helpers --------------------------------------
__device__ __forceinline__ float sigm(float v) {
    return 1.0f / (1.0f + __expf(-v));
}
__device__ __forceinline__ void cp_async16(void* smem_dst, const void* gmem_src) {
    unsigned s = (unsigned)__cvta_generic_to_shared(smem_dst);
    asm volatile("cp.async.cg.shared.global [%0], [%1], 16;" :: "r"(s), "l"(gmem_src) : "memory");
}
#define CP_COMMIT() asm volatile("cp.async.commit_group;" ::: "memory")

// --------------------------- prep kernels -----------------------------------
__global__ void prep_w_kernel(const float* __restrict__ w_ih,
                              const float* __restrict__ w_hh,
                              const float* __restrict__ b_ih,
                              const float* __restrict__ b_hh) {
    int idx = blockIdx.x * blockDim.x + threadIdx.x;
    int n = idx >> 10;
    int k = idx & 1023;
    float v = w_ih[n * 1024 + k];
    if (k < 512) v += w_hh[n * 512 + k];
    g_W16[idx] = __float2half_rn(v);
    if (idx < GATES) g_bias[idx] = b_ih[idx] + b_hh[idx];
}

__global__ void offsets_kernel(const int* __restrict__ batch) {
    int t = blockIdx.x * blockDim.x + threadIdx.x;
    if (t > B_GRAPHS) return;
    int lo = 0, hi = N_NODES;
    while (lo < hi) {
        int mid = (lo + hi) >> 1;
        if (batch[mid] < t) lo = mid + 1; else hi = mid;
    }
    g_off[t] = lo;
}

// Step 0: q_star = 0, h = 0 -> gates = bias (identical for every graph)
__global__ void lstm_init_kernel() {
    int b = blockIdx.x;
    int d = threadIdx.x;
    float i = sigm(g_bias[d]);
    float g = tanhf(g_bias[1024 + d]);
    float o = sigm(g_bias[1536 + d]);
    float c = i * g;
    float h = o * tanhf(c);
    g_c[b * D_IN + d]  = c;
    g_hr[b * 1024 + d] = h;
    g_hr16[b * 1024 + d] = __float2half_rn(h);
}

// ------ GEMM (fp16 HMMA, fp32 accum, 4-stage cp.async): gates = hr @ W^T -----
// M=256, N=2048, K=1024. CTA tile 64x64, 8 warps, warp = 1x2 m16n16k16 tiles.
__global__ void __launch_bounds__(256) gemm_tc_kernel() {
    __shared__ __align__(16) __half sA[GSTAGES][64][40];   // 20 KB
    __shared__ __align__(16) __half sB[GSTAGES][64][40];   // 20 KB

    const int bm = blockIdx.y * 64;        // gridDim.y = 4
    const int bn = blockIdx.x * 64;        // gridDim.x = 32
    const int tid = threadIdx.x;
    const int w   = tid >> 5;
    const int mt  = w & 3;
    const int ng  = w >> 2;

    wmma::fragment<wmma::accumulator, 16, 16, 16, float> cf[2];
    wmma::fill_fragment(cf[0], 0.0f);
    wmma::fill_fragment(cf[1], 0.0f);

    // staging: 64 rows x 32 halves per stage; thread -> (row, 16B segment)
    const int row = tid >> 2;              // 0..63
    const int seg = (tid & 3) * 8;         // halves: 0,8,16,24
    const __half* Ag = g_hr16 + (bm + row) * K_COMB + seg;
    const __half* Bg = g_W16  + (bn + row) * K_COMB + seg;

    auto issue = [&](int ks) {
        const int st = ks & (GSTAGES - 1);
        cp_async16(&sA[st][row][seg], Ag + ks * 32);
        cp_async16(&sB[st][row][seg], Bg + ks * 32);
        CP_COMMIT();
    };
    auto compute = [&](int st) {
        #pragma unroll
        for (int kk = 0; kk < 32; kk += 16) {
            wmma::fragment<wmma::matrix_a, 16, 16, 16, __half, wmma::row_major> af;
            wmma::load_matrix_sync(af, &sA[st][mt * 16][kk], 40);
            #pragma unroll
            for (int t = 0; t < 2; t++) {
                wmma::fragment<wmma::matrix_b, 16, 16, 16, __half, wmma::col_major> bf;
                wmma::load_matrix_sync(bf, &sB[st][(ng * 2 + t) * 16][kk], 40);
                wmma::mma_sync(cf[t], af, bf, cf[t]);
            }
        }
    };

    issue(0); issue(1); issue(2);          // prologue: 3 stages in flight

    int i = 0;
    for (; i < KITERS - 3; i++) {
        asm volatile("cp.async.wait_group 2;" ::: "memory");   // stage i ready
        __syncthreads();                   // visibility + slot (i-1)%4 free
        issue(i + 3);
        compute(i & (GSTAGES - 1));
    }
    asm volatile("cp.async.wait_group 0;" ::: "memory");       // drain tail
    __syncthreads();
    for (; i < KITERS; i++)
        compute(i & (GSTAGES - 1));

    #pragma unroll
    for (int t = 0; t < 2; t++)
        wmma::store_matrix_sync(&g_gates[(bm + mt * 16) * GATES + bn + (ng * 2 + t) * 16],
                                cf[t], GATES, wmma::mem_row_major);
}

// ---------- attention step 0: one block per graph, fp32 + fp16 copy ----------
// Warp-per-node online softmax; col layout slot j*4+c <-> column 128*j+4*lane+c.
__global__ void __launch_bounds__(512, 2) attn0_kernel(const float* __restrict__ x) {
    const int b    = blockIdx.x;
    const int tid  = threadIdx.x;
    const int wid  = tid >> 5;
    const int lane = tid & 31;

    const int s0 = g_off[b];
    const int s1 = g_off[b + 1];

    __shared__ __align__(16) float sm_q[D_IN];
    __shared__ float  sm_m[16], sm_d[16], sm_scale[16];
    __shared__ __align__(16) float4 sm_r[16][128];

    sm_q[tid] = g_hr[b * 1024 + tid];
    __syncthreads();
    const float4* q4 = (const float4*)sm_q;

    float m = -CUDART_INF_F, denom = 0.0f;
    float r[16];
    #pragma unroll
    for (int k = 0; k < 16; k++) r[k] = 0.0f;

    for (int n = s0 + wid; n < s1; n += 16) {
        const float4* xr = (const float4*)(x + (size_t)n * D_IN);
        float xv[16];
        #pragma unroll
        for (int j = 0; j < 4; j++) {
            float4 v = __ldcs(xr + j * 32 + lane);
            xv[j*4+0] = v.x; xv[j*4+1] = v.y;
            xv[j*4+2] = v.z; xv[j*4+3] = v.w;
        }
        {
            uint2* row16 = (uint2*)(g_x16 + (size_t)n * D_IN);
            #pragma unroll
            for (int j = 0; j < 4; j++) {
                __half2 h0 = __floats2half2_rn(xv[j*4+0], xv[j*4+1]);
                __half2 h1 = __floats2half2_rn(xv[j*4+2], xv[j*4+3]);
                uint2 px;
                px.x = *(unsigned*)&h0;
                px.y = *(unsigned*)&h1;
                row16[j * 32 + lane] = px;
            }
        }

        float p = 0.0f;
        #pragma unroll
        for (int j = 0; j < 4; j++) {
            float4 qv = q4[j * 32 + lane];
            p = fmaf(xv[j*4+0], qv.x, p);
            p = fmaf(xv[j*4+1], qv.y, p);
            p = fmaf(xv[j*4+2], qv.z, p);
            p = fmaf(xv[j*4+3], qv.w, p);
        }
        #pragma unroll
        for (int o = 16; o; o >>= 1) p += __shfl_xor_sync(0xffffffffu, p, o);

        const float mn = fmaxf(m, p);
        const float sc = __expf(m - mn);
        const float wg = __expf(p - mn);
        denom = fmaf(denom, sc, wg);
        #pragma unroll
        for (int k = 0; k < 16; k++) r[k] = fmaf(r[k], sc, wg * xv[k]);
        m = mn;
    }

    if (lane == 0) { sm_m[wid] = m; sm_d[wid] = denom; }
    #pragma unroll
    for (int j = 0; j < 4; j++)
        sm_r[wid][j * 32 + lane] =
            make_float4(r[j*4+0], r[j*4+1], r[j*4+2], r[j*4+3]);
    __syncthreads();

    float M = -CUDART_INF_F;
    #pragma unroll
    for (int w = 0; w < 16; w++) M = fmaxf(M, sm_m[w]);
    if (tid < 16)
        sm_scale[tid] = (sm_m[tid] == -CUDART_INF_F) ? 0.0f : __expf(sm_m[tid] - M);
    __syncthreads();

    float Dn = 0.0f, num = 0.0f;
    #pragma unroll
    for (int w = 0; w < 16; w++) {
        Dn  += sm_d[w] * sm_scale[w];
        num  = fmaf(((const float*)sm_r[w])[tid], sm_scale[w], num);
    }
    const float res = num / (Dn + 1e-16f);
    g_hr16[b * 1024 + 512 + tid] = __float2half_rn(res);
}

// ------- attention steps 1..5: LSTM-cell preamble + fp16 sweep ---------------
// Preamble: 512 threads compute h[b] = lstm(gates[b], c[b]) in-place (block b
// exclusively owns graph b -> no races), h -> sm_q + g_hr16 (next GEMM).
// Main: lane owns cols [8*lane,+8) and [256+8*lane,+8). Final step writes out.
__global__ void __launch_bounds__(512, 2) attn16_kernel(float* __restrict__ out) {
    const int b    = blockIdx.x;
    const int tid  = threadIdx.x;
    const int wid  = tid >> 5;
    const int lane = tid & 31;

    const int s0 = g_off[b];
    const int s1 = g_off[b + 1];

    __shared__ __align__(16) float sm_q[D_IN];
    __shared__ float  sm_m[16], sm_d[16], sm_scale[16];
    __shared__ __align__(16) float4 sm_r[16][128];

    // ---- LSTM cell preamble: one element per thread ----
    {
        const float* gr = g_gates + b * GATES + tid;
        const float i = sigm(gr[0]     + g_bias[tid]);
        const float f = sigm(gr[512]   + g_bias[512 + tid]);
        const float g = tanhf(gr[1024] + g_bias[1024 + tid]);
        const float o = sigm(gr[1536]  + g_bias[1536 + tid]);
        const int cidx = b * D_IN + tid;
        const float c = f * g_c[cidx] + i * g;
        g_c[cidx] = c;
        const float h = o * tanhf(c);
        sm_q[tid] = h;
        g_hr16[b * 1024 + tid] = __float2half_rn(h);   // for next step's GEMM
    }
    __syncthreads();

    float qf[16];
    #pragma unroll
    for (int k = 0; k < 8; k++) qf[k]     = sm_q[8 * lane + k];
    #pragma unroll
    for (int k = 0; k < 8; k++) qf[8 + k] = sm_q[256 + 8 * lane + k];

    float m = -CUDART_INF_F, denom = 0.0f;
    float r[16];
    #pragma unroll
    for (int k = 0; k < 16; k++) r[k] = 0.0f;

    for (int n = s0 + wid * 2; n < s1; n += 32) {
        const uint4* rowa = (const uint4*)(g_x16 + (size_t)n * D_IN);
        uint4 a0 = __ldcs(rowa + lane);
        uint4 a1 = __ldcs(rowa + 32 + lane);
        const bool has_b = (n + 1) < s1;
        uint4 b0, b1;
        if (has_b) {
            const uint4* rowb = (const uint4*)(g_x16 + (size_t)(n + 1) * D_IN);
            b0 = __ldcs(rowb + lane);
            b1 = __ldcs(rowb + 32 + lane);
        }

        float xf[16];
        {
            const unsigned* u = (const unsigned*)&a0;
            #pragma unroll
            for (int t = 0; t < 4; t++) {
                float2 f = __half22float2(*(const __half2*)&u[t]);
                xf[t*2+0] = f.x; xf[t*2+1] = f.y;
            }
            const unsigned* v = (const unsigned*)&a1;
            #pragma unroll
            for (int t = 0; t < 4; t++) {
                float2 f = __half22float2(*(const __half2*)&v[t]);
                xf[8+t*2+0] = f.x; xf[8+t*2+1] = f.y;
            }
        }
        float p = 0.0f;
        #pragma unroll
        for (int k = 0; k < 16; k++) p = fmaf(xf[k], qf[k], p);
        #pragma unroll
        for (int o = 16; o; o >>= 1) p += __shfl_xor_sync(0xffffffffu, p, o);
        float mn = fmaxf(m, p);
        float sc = __expf(m - mn);
        float wg = __expf(p - mn);
        denom = fmaf(denom, sc, wg);
        #pragma unroll
        for (int k = 0; k < 16; k++) r[k] = fmaf(r[k], sc, wg * xf[k]);
        m = mn;

        if (has_b) {
            float yf[16];
            {
                const unsigned* u = (const unsigned*)&b0;
                #pragma unroll
                for (int t = 0; t < 4; t++) {
                    float2 f = __half22float2(*(const __half2*)&u[t]);
                    yf[t*2+0] = f.x; yf[t*2+1] = f.y;
                }
                const unsigned* v = (const unsigned*)&b1;
                #pragma unroll
                for (int t = 0; t < 4; t++) {
                    float2 f = __half22float2(*(const __half2*)&v[t]);
                    yf[8+t*2+0] = f.x; yf[8+t*2+1] = f.y;
                }
            }
            float pb = 0.0f;
            #pragma unroll
            for (int k = 0; k < 16; k++) pb = fmaf(yf[k], qf[k], pb);
            #pragma unroll
            for (int o = 16; o; o >>= 1) pb += __shfl_xor_sync(0xffffffffu, pb, o);
            mn = fmaxf(m, pb);
            sc = __expf(m - mn);
            wg = __expf(pb - mn);
            denom = fmaf(denom, sc, wg);
            #pragma unroll
            for (int k = 0; k < 16; k++) r[k] = fmaf(r[k], sc, wg * yf[k]);
            m = mn;
        }
    }

    if (lane == 0) { sm_m[wid] = m; sm_d[wid] = denom; }
    {
        float* dst = (float*)sm_r[wid];
        #pragma unroll
        for (int k = 0; k < 8; k++) dst[8 * lane + k]       = r[k];
        #pragma unroll
        for (int k = 0; k < 8; k++) dst[256 + 8 * lane + k] = r[8 + k];
    }
    __syncthreads();

    float M = -CUDART_INF_F;
    #pragma unroll
    for (int w = 0; w < 16; w++) M = fmaxf(M, sm_m[w]);
    if (tid < 16)
        sm_scale[tid] = (sm_m[tid] == -CUDART_INF_F) ? 0.0f : __expf(sm_m[tid] - M);
    __syncthreads();

    float Dn = 0.0f, num = 0.0f;
    #pragma unroll
    for (int w = 0; w < 16; w++) {
        Dn  += sm_d[w] * sm_scale[w];
        num  = fmaf(((const float*)sm_r[w])[tid], sm_scale[w], num);
    }
    const float res = num / (Dn + 1e-16f);
    g_hr16[b * 1024 + 512 + tid] = __float2half_rn(res);
    if (out) {
        out[b * 1024 + tid]       = sm_q[tid];   // h half (== q this step)
        out[b * 1024 + 512 + tid] = res;         // r half
    }
}

// ------------------------------- launch --------------------------------------
extern "C" void kernel_launch(void* const* d_in, const int* in_sizes, int n_in,
                              void* d_out, int out_size) {
    const float* x     = (const float*)d_in[0];
    const int*   batch = (const int*)d_in[1];
    const float* w_ih  = (const float*)d_in[2];
    const float* w_hh  = (const float*)d_in[3];
    const float* b_ih  = (const float*)d_in[4];
    const float* b_hh  = (const float*)d_in[5];
    float* out = (float*)d_out;

    prep_w_kernel<<<(GATES * K_COMB) / 256, 256>>>(w_ih, w_hh, b_ih, b_hh);
    offsets_kernel<<<2, 160>>>(batch);
    lstm_init_kernel<<<B_GRAPHS, 512>>>();

    for (int s = 0; s < STEPS; s++) {
        if (s > 0)
            gemm_tc_kernel<<<dim3(32, 4), 256>>>();
        if (s == 0)
            attn0_kernel<<<B_GRAPHS, 512>>>(x);
        else
            attn16_kernel<<<B_GRAPHS, 512>>>(s == STEPS - 1 ? out : nullptr);
    }
}

// round 16
// speedup vs baseline: 1.2175x; 1.0141x over previous
#include <cuda_runtime.h>
#include <cuda_fp16.h>
#include <math_constants.h>
#include <mma.h>

using namespace nvcuda;

#define N_NODES   262144
#define D_IN      512
#define B_GRAPHS  256
#define GATES     2048      // 4*D_IN
#define K_COMB    1024      // combined K (h:512 | r:512)
#define STEPS     6
#define KITERS    (K_COMB / 32)   // 32

// ----------------- device scratch (no runtime allocation allowed) -----------
__device__ __align__(16) __half g_W16[GATES * K_COMB];    // fp16 combined weights (4 MB)
__device__ __align__(16) float  g_bias[GATES];
__device__ __align__(16) __half g_hr16[B_GRAPHS * 1024];  // fp16 [h | r] for GEMM
__device__ __align__(16) float  g_c[B_GRAPHS * D_IN];
__device__ __align__(16) float  g_gates[B_GRAPHS * GATES];
__device__ __align__(16) __half g_x16[(size_t)N_NODES * D_IN];  // 256 MB fp16 copy
__device__ int g_off[B_GRAPHS + 1];
__device__ unsigned g_barrier;                             // reset by attn0

// ----------------------------- helpers --------------------------------------
__device__ __forceinline__ float sigm(float v) {
    return 1.0f / (1.0f + __expf(-v));
}
__device__ __forceinline__ void cp_async16(void* smem_dst, const void* gmem_src) {
    unsigned s = (unsigned)__cvta_generic_to_shared(smem_dst);
    asm volatile("cp.async.cg.shared.global [%0], [%1], 16;" :: "r"(s), "l"(gmem_src) : "memory");
}
#define CP_COMMIT() asm volatile("cp.async.commit_group;" ::: "memory")

// Grid-wide barrier: all 256 blocks co-resident (guaranteed by launch_bounds
// occupancy 2 and grid <= 296 slots), so spinning is deadlock-free.
__device__ __forceinline__ void grid_barrier(unsigned target) {
    __syncthreads();
    if (threadIdx.x == 0) {
        __threadfence();
        atomicAdd(&g_barrier, 1u);
        while (*((volatile unsigned*)&g_barrier) < target) { }
        __threadfence();
    }
    __syncthreads();
}

// --------------------------- prep kernel (weights + bias + offsets) ----------
__global__ void prep_w_kernel(const float* __restrict__ w_ih,
                              const float* __restrict__ w_hh,
                              const float* __restrict__ b_ih,
                              const float* __restrict__ b_hh,
                              const int*   __restrict__ batch) {
    int idx = blockIdx.x * blockDim.x + threadIdx.x;
    int n = idx >> 10;
    int k = idx & 1023;
    float v = w_ih[n * 1024 + k];
    if (k < 512) v += w_hh[n * 512 + k];
    g_W16[idx] = __float2half_rn(v);
    if (idx < GATES) g_bias[idx] = b_ih[idx] + b_hh[idx];
    if (idx <= B_GRAPHS) {                    // segment offsets: lower_bound
        int lo = 0, hi = N_NODES;
        while (lo < hi) {
            int mid = (lo + hi) >> 1;
            if (batch[mid] < idx) lo = mid + 1; else hi = mid;
        }
        g_off[idx] = lo;
    }
}

// ---------- attention step 0: one block per graph, fp32 + fp16 copy ----------
// Preamble computes h0 = lstm(0,0,0) from bias directly (no init kernel).
// Warp-per-node online softmax; col layout slot j*4+c <-> column 128*j+4*lane+c.
__global__ void __launch_bounds__(512, 2) attn0_kernel(const float* __restrict__ x) {
    const int b    = blockIdx.x;
    const int tid  = threadIdx.x;
    const int wid  = tid >> 5;
    const int lane = tid & 31;

    const int s0 = g_off[b];
    const int s1 = g_off[b + 1];

    __shared__ __align__(16) float sm_q[D_IN];
    __shared__ float  sm_m[16], sm_d[16], sm_scale[16];
    __shared__ __align__(16) float4 sm_r[16][128];

    // ---- closed-form step-0 LSTM: q0 = h0, c0 stored ----
    {
        float i = sigm(g_bias[tid]);
        float g = tanhf(g_bias[1024 + tid]);
        float o = sigm(g_bias[1536 + tid]);
        float c = i * g;
        float h = o * tanhf(c);
        g_c[b * D_IN + tid] = c;
        sm_q[tid] = h;
        g_hr16[b * 1024 + tid] = __float2half_rn(h);
        if (b == 0 && tid == 0) g_barrier = 0;   // reset for mega kernel
    }
    __syncthreads();
    const float4* q4 = (const float4*)sm_q;

    float m = -CUDART_INF_F, denom = 0.0f;
    float r[16];
    #pragma unroll
    for (int k = 0; k < 16; k++) r[k] = 0.0f;

    for (int n = s0 + wid; n < s1; n += 16) {
        const float4* xr = (const float4*)(x + (size_t)n * D_IN);
        float xv[16];
        #pragma unroll
        for (int j = 0; j < 4; j++) {
            float4 v = __ldcs(xr + j * 32 + lane);
            xv[j*4+0] = v.x; xv[j*4+1] = v.y;
            xv[j*4+2] = v.z; xv[j*4+3] = v.w;
        }
        {
            uint2* row16 = (uint2*)(g_x16 + (size_t)n * D_IN);
            #pragma unroll
            for (int j = 0; j < 4; j++) {
                __half2 h0 = __floats2half2_rn(xv[j*4+0], xv[j*4+1]);
                __half2 h1 = __floats2half2_rn(xv[j*4+2], xv[j*4+3]);
                uint2 px;
                px.x = *(unsigned*)&h0;
                px.y = *(unsigned*)&h1;
                row16[j * 32 + lane] = px;
            }
        }

        float p = 0.0f;
        #pragma unroll
        for (int j = 0; j < 4; j++) {
            float4 qv = q4[j * 32 + lane];
            p = fmaf(xv[j*4+0], qv.x, p);
            p = fmaf(xv[j*4+1], qv.y, p);
            p = fmaf(xv[j*4+2], qv.z, p);
            p = fmaf(xv[j*4+3], qv.w, p);
        }
        #pragma unroll
        for (int o = 16; o; o >>= 1) p += __shfl_xor_sync(0xffffffffu, p, o);

        const float mn = fmaxf(m, p);
        const float sc = __expf(m - mn);
        const float wg = __expf(p - mn);
        denom = fmaf(denom, sc, wg);
        #pragma unroll
        for (int k = 0; k < 16; k++) r[k] = fmaf(r[k], sc, wg * xv[k]);
        m = mn;
    }

    if (lane == 0) { sm_m[wid] = m; sm_d[wid] = denom; }
    #pragma unroll
    for (int j = 0; j < 4; j++)
        sm_r[wid][j * 32 + lane] =
            make_float4(r[j*4+0], r[j*4+1], r[j*4+2], r[j*4+3]);
    __syncthreads();

    float M = -CUDART_INF_F;
    #pragma unroll
    for (int w = 0; w < 16; w++) M = fmaxf(M, sm_m[w]);
    if (tid < 16)
        sm_scale[tid] = (sm_m[tid] == -CUDART_INF_F) ? 0.0f : __expf(sm_m[tid] - M);
    __syncthreads();

    float Dn = 0.0f, num = 0.0f;
    #pragma unroll
    for (int w = 0; w < 16; w++) {
        Dn  += sm_d[w] * sm_scale[w];
        num  = fmaf(((const float*)sm_r[w])[tid], sm_scale[w], num);
    }
    const float res = num / (Dn + 1e-16f);
    g_hr16[b * 1024 + 512 + tid] = __float2half_rn(res);
}

// --------- mega kernel: steps 1..5 (GEMM + LSTM + attention), 1 launch -------
// 256 blocks, all co-resident. Per step: blocks 0..127 run the pipelined HMMA
// GEMM (64x64 tiles); grid barrier; every block runs LSTM preamble + fp16
// sweep for its graph; grid barrier. Cross-block data (gates, hr16) is read
// via L2-only paths (__ldcg / cp.async.cg) since L1 is not coherent in-kernel.
__global__ void __launch_bounds__(512, 2) mega_kernel(float* __restrict__ out) {
    extern __shared__ __align__(16) char smem_raw[];
    // GEMM overlay: sA[4][64][40], sB[4][64][40] halves (40960 B total)
    __half (*sA)[64][40] = (__half (*)[64][40])smem_raw;
    __half (*sB)[64][40] = (__half (*)[64][40])(smem_raw + 4 * 64 * 40 * 2);
    // attention overlay (35008 B)
    float* sm_q    = (float*)smem_raw;                     // 512 f
    float* sm_m    = (float*)(smem_raw + 2048);            // 16 f
    float* sm_d    = (float*)(smem_raw + 2048 + 64);       // 16 f
    float* sm_sc   = (float*)(smem_raw + 2048 + 128);      // 16 f
    float* sm_rbuf = (float*)(smem_raw + 2048 + 192);      // 16*512 f

    const int bid  = blockIdx.x;
    const int tid  = threadIdx.x;
    const int wid  = tid >> 5;
    const int lane = tid & 31;
    const int b    = bid;                   // graph id
    const int s0   = g_off[b];
    const int s1   = g_off[b + 1];

    // GEMM role (blocks 0..127): tile (gbm, gbn) of 64x64
    const int gbm = (bid >> 5) * 64;
    const int gbn = (bid & 31) * 64;
    const int lt   = tid & 255;
    const int lrow = lt >> 2;               // 0..63
    const int lcol = (lt & 3) * 8;          // halves 0,8,16,24
    const bool isA = (tid < 256);
    const __half* gsrc = isA ? (g_hr16 + (gbm + lrow) * K_COMB + lcol)
                             : (g_W16  + (gbn + lrow) * K_COMB + lcol);
    const int mt = wid & 3, nt = wid >> 2;  // warp -> 16x16 output tile

    unsigned bar = 0;

    for (int s = 1; s <= STEPS - 1; s++) {
        // ================= GEMM phase: gates = hr16 @ W^T ====================
        if (bid < 128) {
            wmma::fragment<wmma::accumulator, 16, 16, 16, float> cf;
            wmma::fill_fragment(cf, 0.0f);

            auto issue = [&](int ks) {
                const int st = ks & 3;
                __half* dst = isA ? &sA[st][lrow][lcol] : &sB[st][lrow][lcol];
                cp_async16(dst, gsrc + ks * 32);
                CP_COMMIT();
            };
            auto compute = [&](int st) {
                #pragma unroll
                for (int kk = 0; kk < 32; kk += 16) {
                    wmma::fragment<wmma::matrix_a, 16, 16, 16, __half, wmma::row_major> af;
                    wmma::load_matrix_sync(af, &sA[st][mt * 16][kk], 40);
                    wmma::fragment<wmma::matrix_b, 16, 16, 16, __half, wmma::col_major> bf;
                    wmma::load_matrix_sync(bf, &sB[st][nt * 16][kk], 40);
                    wmma::mma_sync(cf, af, bf, cf);
                }
            };

            issue(0); issue(1); issue(2);
            int i = 0;
            for (; i < KITERS - 3; i++) {
                asm volatile("cp.async.wait_group 2;" ::: "memory");
                __syncthreads();
                issue(i + 3);
                compute(i & 3);
            }
            asm volatile("cp.async.wait_group 0;" ::: "memory");
            __syncthreads();
            for (; i < KITERS; i++) compute(i & 3);

            wmma::store_matrix_sync(&g_gates[(gbm + mt * 16) * GATES + gbn + nt * 16],
                                    cf, GATES, wmma::mem_row_major);
        }
        bar += B_GRAPHS; grid_barrier(bar);

        // ================= attention phase (graph b) =========================
        // LSTM cell preamble (gates via L2: other blocks wrote them)
        {
            const float* gr = g_gates + b * GATES + tid;
            const float iv = sigm(__ldcg(gr)          + g_bias[tid]);
            const float fv = sigm(__ldcg(gr + 512)    + g_bias[512 + tid]);
            const float gv = tanhf(__ldcg(gr + 1024)  + g_bias[1024 + tid]);
            const float ov = sigm(__ldcg(gr + 1536)   + g_bias[1536 + tid]);
            const int cidx = b * D_IN + tid;
            const float c = fv * g_c[cidx] + iv * gv;
            g_c[cidx] = c;
            const float h = ov * tanhf(c);
            sm_q[tid] = h;
            g_hr16[b * 1024 + tid] = __float2half_rn(h);
        }
        __syncthreads();

        float qf[16];
        #pragma unroll
        for (int k = 0; k < 8; k++) qf[k]     = sm_q[8 * lane + k];
        #pragma unroll
        for (int k = 0; k < 8; k++) qf[8 + k] = sm_q[256 + 8 * lane + k];

        float m = -CUDART_INF_F, denom = 0.0f;
        float r[16];
        #pragma unroll
        for (int k = 0; k < 16; k++) r[k] = 0.0f;

        for (int n = s0 + wid * 2; n < s1; n += 32) {
            const uint4* rowa = (const uint4*)(g_x16 + (size_t)n * D_IN);
            uint4 a0 = __ldcs(rowa + lane);
            uint4 a1 = __ldcs(rowa + 32 + lane);
            const bool has_b = (n + 1) < s1;
            uint4 b0, b1;
            if (has_b) {
                const uint4* rowb = (const uint4*)(g_x16 + (size_t)(n + 1) * D_IN);
                b0 = __ldcs(rowb + lane);
                b1 = __ldcs(rowb + 32 + lane);
            }

            float xf[16];
            {
                const unsigned* u = (const unsigned*)&a0;
                #pragma unroll
                for (int t = 0; t < 4; t++) {
                    float2 f = __half22float2(*(const __half2*)&u[t]);
                    xf[t*2+0] = f.x; xf[t*2+1] = f.y;
                }
                const unsigned* v = (const unsigned*)&a1;
                #pragma unroll
                for (int t = 0; t < 4; t++) {
                    float2 f = __half22float2(*(const __half2*)&v[t]);
                    xf[8+t*2+0] = f.x; xf[8+t*2+1] = f.y;
                }
            }
            float p = 0.0f;
            #pragma unroll
            for (int k = 0; k < 16; k++) p = fmaf(xf[k], qf[k], p);
            #pragma unroll
            for (int o = 16; o; o >>= 1) p += __shfl_xor_sync(0xffffffffu, p, o);
            float mn = fmaxf(m, p);
            float sc = __expf(m - mn);
            float wg = __expf(p - mn);
            denom = fmaf(denom, sc, wg);
            #pragma unroll
            for (int k = 0; k < 16; k++) r[k] = fmaf(r[k], sc, wg * xf[k]);
            m = mn;

            if (has_b) {
                float yf[16];
                {
                    const unsigned* u = (const unsigned*)&b0;
                    #pragma unroll
                    for (int t = 0; t < 4; t++) {
                        float2 f = __half22float2(*(const __half2*)&u[t]);
                        yf[t*2+0] = f.x; yf[t*2+1] = f.y;
                    }
                    const unsigned* v = (const unsigned*)&b1;
                    #pragma unroll
                    for (int t = 0; t < 4; t++) {
                        float2 f = __half22float2(*(const __half2*)&v[t]);
                        yf[8+t*2+0] = f.x; yf[8+t*2+1] = f.y;
                    }
                }
                float pb = 0.0f;
                #pragma unroll
                for (int k = 0; k < 16; k++) pb = fmaf(yf[k], qf[k], pb);
                #pragma unroll
                for (int o = 16; o; o >>= 1) pb += __shfl_xor_sync(0xffffffffu, pb, o);
                mn = fmaxf(m, pb);
                sc = __expf(m - mn);
                wg = __expf(pb - mn);
                denom = fmaf(denom, sc, wg);
                #pragma unroll
                for (int k = 0; k < 16; k++) r[k] = fmaf(r[k], sc, wg * yf[k]);
                m = mn;
            }
        }

        if (lane == 0) { sm_m[wid] = m; sm_d[wid] = denom; }
        {
            float* dst = sm_rbuf + wid * 512;
            #pragma unroll
            for (int k = 0; k < 8; k++) dst[8 * lane + k]       = r[k];
            #pragma unroll
            for (int k = 0; k < 8; k++) dst[256 + 8 * lane + k] = r[8 + k];
        }
        __syncthreads();

        float M = -CUDART_INF_F;
        #pragma unroll
        for (int w = 0; w < 16; w++) M = fmaxf(M, sm_m[w]);
        if (tid < 16)
            sm_sc[tid] = (sm_m[tid] == -CUDART_INF_F) ? 0.0f : __expf(sm_m[tid] - M);
        __syncthreads();

        float Dn = 0.0f, num = 0.0f;
        #pragma unroll
        for (int w = 0; w < 16; w++) {
            Dn  += sm_d[w] * sm_sc[w];
            num  = fmaf(sm_rbuf[w * 512 + tid], sm_sc[w], num);
        }
        const float res = num / (Dn + 1e-16f);
        g_hr16[b * 1024 + 512 + tid] = __float2half_rn(res);

        if (s == STEPS - 1) {
            out[b * 1024 + tid]       = sm_q[tid];   // h half
            out[b * 1024 + 512 + tid] = res;         // r half
        } else {
            bar += B_GRAPHS; grid_barrier(bar);
        }
    }
}

// ------------------------------- launch --------------------------------------
extern "C" void kernel_launch(void* const* d_in, const int* in_sizes, int n_in,
                              void* d_out, int out_size) {
    const float* x     = (const float*)d_in[0];
    const int*   batch = (const int*)d_in[1];
    const float* w_ih  = (const float*)d_in[2];
    const float* w_hh  = (const float*)d_in[3];
    const float* b_ih  = (const float*)d_in[4];
    const float* b_hh  = (const float*)d_in[5];
    float* out = (float*)d_out;

    const int mega_smem = 4 * 64 * 40 * 2 * 2;   // 40960 B (gemm overlay is max)

    prep_w_kernel<<<(GATES * K_COMB) / 256, 256>>>(w_ih, w_hh, b_ih, b_hh, batch);
    attn0_kernel<<<B_GRAPHS, 512>>>(x);
    mega_kernel<<<B_GRAPHS, 512, mega_smem>>>(out);
}